// round 1
// baseline (speedup 1.0000x reference)
#include <cuda_runtime.h>
#include <cstdint>

#define E_DIM 1024
#define T_DIM 8192
#define DV 128

// Scratch: QKV for the 16384 dilated tokens, layout [row][384] = Q|K|V.
// row r = b*4096 + j*64 + l  (group g = b*64+j has 64 contiguous rows)
__device__ float g_qkv[16384 * 384];

__global__ __launch_bounds__(256) void zero_out_kernel(float4* out, int n4) {
    int i = blockIdx.x * blockDim.x + threadIdx.x;
    int stride = gridDim.x * blockDim.x;
    float4 z = make_float4(0.f, 0.f, 0.f, 0.f);
    for (; i < n4; i += stride) out[i] = z;
}

// C[16384,384] = Xdil[16384,1024] * W^T, W stacked (Wq|Wk|Wv), fp32 SIMT GEMM.
// BM=128, BN=64, BK=16, 256 threads, 8x4 micro-tile per thread.
__global__ __launch_bounds__(256) void qkv_gemm_kernel(
    const float* __restrict__ x,
    const float* __restrict__ Wq,
    const float* __restrict__ Wk,
    const float* __restrict__ Wv)
{
    __shared__ float As[16][129];   // [k][m], padded
    __shared__ float Bs[16][68];    // [k][n], padded

    const int ntile = blockIdx.x;            // 0..5 -> which 64-col slab
    const int m0 = blockIdx.y * 128;
    const float* W = (ntile < 2) ? Wq : (ntile < 4) ? Wk : Wv;
    const int nloc0 = (ntile & 1) * 64;      // row offset inside the weight
    const int ncol0 = ntile * 64;            // column in g_qkv
    const int tid = threadIdx.x;
    const int tm = tid >> 4;                 // 0..15 -> 8 rows each
    const int tn = tid & 15;                 // 0..15 -> 4 cols each

    // loader indices
    const int lrow = tid >> 2;               // 0..63
    const int lk4  = (tid & 3) * 4;          // 0,4,8,12

    // dilated gather: global row r -> x_in[b, l*128 + j, :]
    const float* xrow0;
    const float* xrow1;
    {
        int r0 = m0 + lrow;
        int r1 = m0 + lrow + 64;
        int b0 = r0 >> 12, j0 = (r0 >> 6) & 63, l0 = r0 & 63;
        int b1 = r1 >> 12, j1 = (r1 >> 6) & 63, l1 = r1 & 63;
        xrow0 = x + ((size_t)b0 * T_DIM + (size_t)l0 * 128 + j0) * E_DIM;
        xrow1 = x + ((size_t)b1 * T_DIM + (size_t)l1 * 128 + j1) * E_DIM;
    }
    const float* wrow = W + (size_t)(nloc0 + lrow) * E_DIM;

    float acc[8][4];
    #pragma unroll
    for (int i = 0; i < 8; i++)
        #pragma unroll
        for (int j = 0; j < 4; j++) acc[i][j] = 0.f;

    for (int k0 = 0; k0 < E_DIM; k0 += 16) {
        float4 a0 = *reinterpret_cast<const float4*>(xrow0 + k0 + lk4);
        float4 a1 = *reinterpret_cast<const float4*>(xrow1 + k0 + lk4);
        float4 bv = *reinterpret_cast<const float4*>(wrow + k0 + lk4);
        __syncthreads();
        As[lk4+0][lrow]      = a0.x; As[lk4+1][lrow]      = a0.y;
        As[lk4+2][lrow]      = a0.z; As[lk4+3][lrow]      = a0.w;
        As[lk4+0][lrow + 64] = a1.x; As[lk4+1][lrow + 64] = a1.y;
        As[lk4+2][lrow + 64] = a1.z; As[lk4+3][lrow + 64] = a1.w;
        Bs[lk4+0][lrow] = bv.x; Bs[lk4+1][lrow] = bv.y;
        Bs[lk4+2][lrow] = bv.z; Bs[lk4+3][lrow] = bv.w;
        __syncthreads();
        #pragma unroll
        for (int kk = 0; kk < 16; kk++) {
            float ra[8], rb[4];
            #pragma unroll
            for (int i = 0; i < 8; i++) ra[i] = As[kk][tm*8 + i];
            #pragma unroll
            for (int j = 0; j < 4; j++) rb[j] = Bs[kk][tn*4 + j];
            #pragma unroll
            for (int i = 0; i < 8; i++)
                #pragma unroll
                for (int j = 0; j < 4; j++)
                    acc[i][j] = fmaf(ra[i], rb[j], acc[i][j]);
        }
    }

    #pragma unroll
    for (int i = 0; i < 8; i++) {
        int row = m0 + tm*8 + i;
        float4 v = make_float4(acc[i][0], acc[i][1], acc[i][2], acc[i][3]);
        *reinterpret_cast<float4*>(&g_qkv[(size_t)row * 384 + ncol0 + tn*4]) = v;
    }
}

// One block per (b, j) group: S = K Q^T (64x64, dot over 128),
// mask(k>=o) -> +P[128k,128o] bias -> *1/sqrt(128) -> softmax over k -> att = S^T-weighted V.
__global__ __launch_bounds__(256) void attn_kernel(
    const float* __restrict__ P, float* __restrict__ out)
{
    extern __shared__ float sm[];
    float* Ks = sm;                     // [64][128]
    float* Vs = Ks + 64 * 128;          // [64][128]
    float* Qt = Vs + 64 * 128;          // [128][68] transposed: Qt[p][o]
    float* S  = Qt + 128 * 68;          // [64][65]
    const int g = blockIdx.x;           // b*64 + j
    const int bb = g >> 6, jseg = g & 63;
    const int tid = threadIdx.x;
    const float* base = g_qkv + (size_t)g * 64 * 384;

    // Load Q (transposed), K, V into shared
    for (int idx = tid; idx < 64 * 32; idx += 256) {
        int row = idx >> 5;
        int c4 = (idx & 31) * 4;
        const float* rp = base + (size_t)row * 384;
        float4 qv = *reinterpret_cast<const float4*>(rp + c4);
        float4 kv = *reinterpret_cast<const float4*>(rp + 128 + c4);
        float4 vv = *reinterpret_cast<const float4*>(rp + 256 + c4);
        *reinterpret_cast<float4*>(Ks + row * 128 + c4) = kv;
        *reinterpret_cast<float4*>(Vs + row * 128 + c4) = vv;
        Qt[(c4 + 0) * 68 + row] = qv.x;
        Qt[(c4 + 1) * 68 + row] = qv.y;
        Qt[(c4 + 2) * 68 + row] = qv.z;
        Qt[(c4 + 3) * 68 + row] = qv.w;
    }
    __syncthreads();

    // S[k][o] = dot(K[k], Q[o]); then mask + bias + scale
    {
        const int tk = tid >> 4, to = tid & 15;   // 4x4 micro-tile
        float acc[4][4];
        #pragma unroll
        for (int i = 0; i < 4; i++)
            #pragma unroll
            for (int j = 0; j < 4; j++) acc[i][j] = 0.f;
        for (int p = 0; p < 128; p++) {
            float rk[4], rq[4];
            #pragma unroll
            for (int i = 0; i < 4; i++) rk[i] = Ks[(tk*4 + i) * 128 + p];
            #pragma unroll
            for (int j = 0; j < 4; j++) rq[j] = Qt[p * 68 + to*4 + j];
            #pragma unroll
            for (int i = 0; i < 4; i++)
                #pragma unroll
                for (int j = 0; j < 4; j++)
                    acc[i][j] = fmaf(rk[i], rq[j], acc[i][j]);
        }
        const float nf = 0.08838834764831845f;  // 1/sqrt(128)
        #pragma unroll
        for (int i = 0; i < 4; i++) {
            int k = tk*4 + i;
            #pragma unroll
            for (int j = 0; j < 4; j++) {
                int o = to*4 + j;
                // reference order: mask first, THEN add bias, then scale
                float v = (k >= o) ? acc[i][j] : -10000.0f;
                v += P[(size_t)(k * 128) * T_DIM + (size_t)(o * 128)];
                S[k * 65 + o] = v * nf;
            }
        }
    }
    __syncthreads();

    // softmax over k (per query column o)
    if (tid < 64) {
        int o = tid;
        float mx = -3.402823466e38f;
        for (int k = 0; k < 64; k++) mx = fmaxf(mx, S[k * 65 + o]);
        float sum = 0.f;
        for (int k = 0; k < 64; k++) {
            float e = __expf(S[k * 65 + o] - mx);
            S[k * 65 + o] = e;
            sum += e;
        }
        float inv = 1.0f / sum;
        for (int k = 0; k < 64; k++) S[k * 65 + o] *= inv;
    }
    __syncthreads();

    // att[d][m] = sum_k S[k][d] * V[k][m]; write to out[b, 2*(j*64+d), m]
    {
        const int td = tid >> 4;       // d0 = td*4
        const int tmm = tid & 15;      // m0 = tmm*8
        float acc[4][8];
        #pragma unroll
        for (int i = 0; i < 4; i++)
            #pragma unroll
            for (int j = 0; j < 8; j++) acc[i][j] = 0.f;
        for (int k = 0; k < 64; k++) {
            float rs[4];
            #pragma unroll
            for (int i = 0; i < 4; i++) rs[i] = S[k * 65 + td*4 + i];
            float4 v0 = *reinterpret_cast<const float4*>(Vs + k * 128 + tmm*8);
            float4 v1 = *reinterpret_cast<const float4*>(Vs + k * 128 + tmm*8 + 4);
            float rv[8] = {v0.x, v0.y, v0.z, v0.w, v1.x, v1.y, v1.z, v1.w};
            #pragma unroll
            for (int i = 0; i < 4; i++)
                #pragma unroll
                for (int j = 0; j < 8; j++)
                    acc[i][j] = fmaf(rs[i], rv[j], acc[i][j]);
        }
        #pragma unroll
        for (int i = 0; i < 4; i++) {
            int d = td*4 + i;
            size_t orow = (size_t)bb * T_DIM + 2 * ((size_t)jseg * 64 + d);
            float* op = out + orow * DV + tmm*8;
            *reinterpret_cast<float4*>(op)     = make_float4(acc[i][0], acc[i][1], acc[i][2], acc[i][3]);
            *reinterpret_cast<float4*>(op + 4) = make_float4(acc[i][4], acc[i][5], acc[i][6], acc[i][7]);
        }
    }
}

extern "C" void kernel_launch(void* const* d_in, const int* in_sizes, int n_in,
                              void* d_out, int out_size) {
    const float* x  = (const float*)d_in[0];   // x_in  [4, 8192, 1024]
    const float* P  = (const float*)d_in[1];   // P     [8192, 8192]
    const float* Wk = (const float*)d_in[2];   // Wk    [128, 1024]
    const float* Wq = (const float*)d_in[3];   // Wq    [128, 1024]
    const float* Wv = (const float*)d_in[4];   // Wv    [128, 1024]
    float* out = (float*)d_out;                // [4, 8192, 128] fp32

    // 1) zero the whole output (odd rows stay zero; even rows get overwritten)
    zero_out_kernel<<<1024, 256>>>((float4*)out, out_size / 4);

    // 2) fused QKV projection for the 16384 dilated tokens
    dim3 gg(6, 128);
    qkv_gemm_kernel<<<gg, 256>>>(x, Wq, Wk, Wv);

    // 3) per-(b,j) attention
    int smem = (64*128 * 2 + 128*68 + 64*65) * (int)sizeof(float);  // 116,992 B
    cudaFuncSetAttribute(attn_kernel, cudaFuncAttributeMaxDynamicSharedMemorySize, smem);
    attn_kernel<<<256, 256, smem>>>(P, out);
}

// round 3
// speedup vs baseline: 1.8458x; 1.8458x over previous
#include <cuda_runtime.h>
#include <cuda_bf16.h>
#include <cstdint>

#define E_DIM 1024
#define T_DIM 8192
#define DV 128

// Scratch: QKV for the 16384 dilated tokens, layout [row][384] = Q|K|V.
__device__ float g_qkv[16384 * 384];
// Pre-split weights, rows 0-127=Wq, 128-255=Wk, 256-383=Wv
__device__ __nv_bfloat16 g_whi[384 * 1024];
__device__ __nv_bfloat16 g_wlo[384 * 1024];

__device__ __forceinline__ uint32_t smem_u32(const void* p) {
    uint32_t a;
    asm("{ .reg .u64 t; cvta.to.shared.u64 t, %1; cvt.u32.u64 %0, t; }" : "=r"(a) : "l"(p));
    return a;
}

#define LDSM4(r, addr) \
    asm volatile("ldmatrix.sync.aligned.m8n8.x4.shared.b16 {%0,%1,%2,%3}, [%4];" \
        : "=r"((r)[0]), "=r"((r)[1]), "=r"((r)[2]), "=r"((r)[3]) : "r"(addr))

#define MMA16816(c, a, b0, b1) \
    asm volatile("mma.sync.aligned.m16n8k16.row.col.f32.bf16.bf16.f32 " \
        "{%0,%1,%2,%3}, {%4,%5,%6,%7}, {%8,%9}, {%0,%1,%2,%3};" \
        : "+f"((c)[0]), "+f"((c)[1]), "+f"((c)[2]), "+f"((c)[3]) \
        : "r"((a)[0]), "r"((a)[1]), "r"((a)[2]), "r"((a)[3]), "r"(b0), "r"(b1))

__global__ __launch_bounds__(256) void zero_out_kernel(float4* out, int n4) {
    int i = blockIdx.x * blockDim.x + threadIdx.x;
    int stride = gridDim.x * blockDim.x;
    float4 z = make_float4(0.f, 0.f, 0.f, 0.f);
    for (; i < n4; i += stride) out[i] = z;
}

__global__ __launch_bounds__(256) void prep_w_kernel(
    const float* __restrict__ Wq, const float* __restrict__ Wk, const float* __restrict__ Wv)
{
    int i = blockIdx.x * blockDim.x + threadIdx.x;
    if (i >= 384 * 1024) return;
    int r = i >> 10;
    const float* W = (r < 128) ? Wq : (r < 256) ? Wk : Wv;
    float v = W[(size_t)(r & 127) * 1024 + (i & 1023)];
    __nv_bfloat16 h = __float2bfloat16(v);
    g_whi[i] = h;
    g_wlo[i] = __float2bfloat16(v - __bfloat162float(h));
}

// C[16384, 384] = Xdil * W^T via mma.sync bf16 3-split, fp32 accum.
// CTA tile 128(M) x 128(N), BK=32, double-buffered smem.
// Smem stage layout (stride 80B rows, 128 rows each):
//   Ahi @0, Alo @10240, Bhi @20480, Blo @30720; stage size 40960.
__global__ __launch_bounds__(256) void qkv_gemm_mma(const float* __restrict__ x)
{
    extern __shared__ char dsm[];              // 2 * 40960 = 81920 B
    const uint32_t smem_base = smem_u32(dsm);
    const int tid = threadIdx.x;
    const int warp = tid >> 5, lane = tid & 31;
    const int m0 = blockIdx.x * 128;
    const int nbase = blockIdx.y * 128;        // 0=Q, 128=K, 256=V

    // ---- loader mapping: 2 threads per row, 16 elements each ----
    const int lrow = tid >> 1;                 // 0..127
    const int cpos = (tid & 1) * 16;           // 0 or 16
    const float* arow;
    {
        int r = m0 + lrow;
        int b = r >> 12, j = (r >> 6) & 63, l = r & 63;
        arow = x + ((size_t)b * T_DIM + (size_t)l * 128 + j) * E_DIM + cpos;
    }
    const __nv_bfloat16* bhrow = g_whi + (size_t)(nbase + lrow) * 1024 + cpos;
    const __nv_bfloat16* blrow = g_wlo + (size_t)(nbase + lrow) * 1024 + cpos;

    const uint32_t a_st = smem_base + lrow * 80 + cpos * 2;   // + stage*40960
    const uint32_t b_st = a_st + 20480;

    // ---- compute mapping: warp grid 4(M) x 2(N), warp tile 32x64 ----
    const int m_off = (warp >> 1) * 32;
    const int n_off = (warp & 1) * 64;

    float acc[2][8][4];
    #pragma unroll
    for (int i = 0; i < 2; i++)
        #pragma unroll
        for (int j = 0; j < 8; j++)
            #pragma unroll
            for (int k = 0; k < 4; k++) acc[i][j][k] = 0.f;

    // helper lambdas as macros via code blocks
    float4 af[4]; uint4 bhf[2], blf[2];

    // prologue: load chunk 0 and store to stage 0
    {
        #pragma unroll
        for (int q = 0; q < 4; q++) af[q] = *reinterpret_cast<const float4*>(arow + q * 4);
        bhf[0] = *reinterpret_cast<const uint4*>(bhrow);
        bhf[1] = *reinterpret_cast<const uint4*>(bhrow + 8);
        blf[0] = *reinterpret_cast<const uint4*>(blrow);
        blf[1] = *reinterpret_cast<const uint4*>(blrow + 8);
        float vals[16] = {af[0].x, af[0].y, af[0].z, af[0].w, af[1].x, af[1].y, af[1].z, af[1].w,
                          af[2].x, af[2].y, af[2].z, af[2].w, af[3].x, af[3].y, af[3].z, af[3].w};
        uint32_t hi[8], lo[8];
        #pragma unroll
        for (int q = 0; q < 8; q++) {
            float a = vals[2 * q], b = vals[2 * q + 1];
            __nv_bfloat162 h = __floats2bfloat162_rn(a, b);
            __nv_bfloat162 l = __floats2bfloat162_rn(a - __bfloat162float(h.x),
                                                     b - __bfloat162float(h.y));
            hi[q] = *reinterpret_cast<uint32_t*>(&h);
            lo[q] = *reinterpret_cast<uint32_t*>(&l);
        }
        *reinterpret_cast<uint4*>(dsm + (a_st - smem_base))          = make_uint4(hi[0], hi[1], hi[2], hi[3]);
        *reinterpret_cast<uint4*>(dsm + (a_st - smem_base) + 16)     = make_uint4(hi[4], hi[5], hi[6], hi[7]);
        *reinterpret_cast<uint4*>(dsm + (a_st - smem_base) + 10240)  = make_uint4(lo[0], lo[1], lo[2], lo[3]);
        *reinterpret_cast<uint4*>(dsm + (a_st - smem_base) + 10256)  = make_uint4(lo[4], lo[5], lo[6], lo[7]);
        *reinterpret_cast<uint4*>(dsm + (b_st - smem_base))          = bhf[0];
        *reinterpret_cast<uint4*>(dsm + (b_st - smem_base) + 16)     = bhf[1];
        *reinterpret_cast<uint4*>(dsm + (b_st - smem_base) + 10240)  = blf[0];
        *reinterpret_cast<uint4*>(dsm + (b_st - smem_base) + 10256)  = blf[1];
    }
    __syncthreads();

    for (int c = 0; c < 32; c++) {
        const int cur = c & 1;
        const uint32_t stage = smem_base + cur * 40960;

        // prefetch next chunk into regs
        if (c < 31) {
            const int kc = (c + 1) * 32;
            #pragma unroll
            for (int q = 0; q < 4; q++) af[q] = *reinterpret_cast<const float4*>(arow + kc + q * 4);
            bhf[0] = *reinterpret_cast<const uint4*>(bhrow + kc);
            bhf[1] = *reinterpret_cast<const uint4*>(bhrow + kc + 8);
            blf[0] = *reinterpret_cast<const uint4*>(blrow + kc);
            blf[1] = *reinterpret_cast<const uint4*>(blrow + kc + 8);
        }

        // compute on current stage
        #pragma unroll
        for (int kst = 0; kst < 2; kst++) {
            uint32_t ah[2][4], al[2][4];
            #pragma unroll
            for (int mt = 0; mt < 2; mt++) {
                uint32_t ra = stage + (m_off + mt * 16 + (lane & 15)) * 80
                            + kst * 32 + (lane >> 4) * 16;
                LDSM4(ah[mt], ra);
                LDSM4(al[mt], ra + 10240);
            }
            #pragma unroll
            for (int nh = 0; nh < 2; nh++) {
                uint32_t bh[2][4], bl[2][4];
                #pragma unroll
                for (int q = 0; q < 2; q++) {
                    uint32_t rb = stage + 20480
                                + (n_off + nh * 32 + q * 16 + (lane & 15)) * 80
                                + kst * 32 + (lane >> 4) * 16;
                    LDSM4(bh[q], rb);
                    LDSM4(bl[q], rb + 10240);
                }
                #pragma unroll
                for (int mt = 0; mt < 2; mt++)
                    #pragma unroll
                    for (int t = 0; t < 4; t++) {
                        const int q = t >> 1, s = t & 1;
                        const int nt = nh * 4 + q * 2 + s;
                        MMA16816(acc[mt][nt], ah[mt], bh[q][s], bh[q][s + 2]);
                        MMA16816(acc[mt][nt], ah[mt], bl[q][s], bl[q][s + 2]);
                        MMA16816(acc[mt][nt], al[mt], bh[q][s], bh[q][s + 2]);
                    }
            }
        }

        // store prefetched chunk into other stage
        if (c < 31) {
            char* nst = dsm + ((c + 1) & 1) * 40960;
            float vals[16] = {af[0].x, af[0].y, af[0].z, af[0].w, af[1].x, af[1].y, af[1].z, af[1].w,
                              af[2].x, af[2].y, af[2].z, af[2].w, af[3].x, af[3].y, af[3].z, af[3].w};
            uint32_t hi[8], lo[8];
            #pragma unroll
            for (int q = 0; q < 8; q++) {
                float a = vals[2 * q], b = vals[2 * q + 1];
                __nv_bfloat162 h = __floats2bfloat162_rn(a, b);
                __nv_bfloat162 l = __floats2bfloat162_rn(a - __bfloat162float(h.x),
                                                         b - __bfloat162float(h.y));
                hi[q] = *reinterpret_cast<uint32_t*>(&h);
                lo[q] = *reinterpret_cast<uint32_t*>(&l);
            }
            char* abase = nst + lrow * 80 + cpos * 2;
            *reinterpret_cast<uint4*>(abase)          = make_uint4(hi[0], hi[1], hi[2], hi[3]);
            *reinterpret_cast<uint4*>(abase + 16)     = make_uint4(hi[4], hi[5], hi[6], hi[7]);
            *reinterpret_cast<uint4*>(abase + 10240)  = make_uint4(lo[0], lo[1], lo[2], lo[3]);
            *reinterpret_cast<uint4*>(abase + 10256)  = make_uint4(lo[4], lo[5], lo[6], lo[7]);
            char* bbase = abase + 20480;
            *reinterpret_cast<uint4*>(bbase)          = bhf[0];
            *reinterpret_cast<uint4*>(bbase + 16)     = bhf[1];
            *reinterpret_cast<uint4*>(bbase + 10240)  = blf[0];
            *reinterpret_cast<uint4*>(bbase + 10256)  = blf[1];
        }
        __syncthreads();
    }

    // epilogue: D fragment m16n8 -> g_qkv
    #pragma unroll
    for (int mt = 0; mt < 2; mt++) {
        #pragma unroll
        for (int nt = 0; nt < 8; nt++) {
            int row0 = m0 + m_off + mt * 16 + (lane >> 2);
            int col = nbase + n_off + nt * 8 + (lane & 3) * 2;
            float* p0 = &g_qkv[(size_t)row0 * 384 + col];
            float* p1 = &g_qkv[(size_t)(row0 + 8) * 384 + col];
            *reinterpret_cast<float2*>(p0) = make_float2(acc[mt][nt][0], acc[mt][nt][1]);
            *reinterpret_cast<float2*>(p1) = make_float2(acc[mt][nt][2], acc[mt][nt][3]);
        }
    }
}

// One block per (b, j) group: S = K Q^T, mask -> +P bias -> scale -> softmax over k -> att.
__global__ __launch_bounds__(256) void attn_kernel(
    const float* __restrict__ P, float* __restrict__ out)
{
    extern __shared__ float sm[];
    float* Ks = sm;                     // [64][128]
    float* Vs = Ks + 64 * 128;          // [64][128]
    float* Qt = Vs + 64 * 128;          // [128][68]
    float* S  = Qt + 128 * 68;          // [64][65]
    const int g = blockIdx.x;
    const int bb = g >> 6, jseg = g & 63;
    const int tid = threadIdx.x;
    const float* base = g_qkv + (size_t)g * 64 * 384;

    for (int idx = tid; idx < 64 * 32; idx += 256) {
        int row = idx >> 5;
        int c4 = (idx & 31) * 4;
        const float* rp = base + (size_t)row * 384;
        float4 qv = *reinterpret_cast<const float4*>(rp + c4);
        float4 kv = *reinterpret_cast<const float4*>(rp + 128 + c4);
        float4 vv = *reinterpret_cast<const float4*>(rp + 256 + c4);
        *reinterpret_cast<float4*>(Ks + row * 128 + c4) = kv;
        *reinterpret_cast<float4*>(Vs + row * 128 + c4) = vv;
        Qt[(c4 + 0) * 68 + row] = qv.x;
        Qt[(c4 + 1) * 68 + row] = qv.y;
        Qt[(c4 + 2) * 68 + row] = qv.z;
        Qt[(c4 + 3) * 68 + row] = qv.w;
    }
    __syncthreads();

    {
        const int tk = tid >> 4, to = tid & 15;
        float acc[4][4];
        #pragma unroll
        for (int i = 0; i < 4; i++)
            #pragma unroll
            for (int j = 0; j < 4; j++) acc[i][j] = 0.f;
        for (int p = 0; p < 128; p++) {
            float rk[4], rq[4];
            #pragma unroll
            for (int i = 0; i < 4; i++) rk[i] = Ks[(tk * 4 + i) * 128 + p];
            #pragma unroll
            for (int j = 0; j < 4; j++) rq[j] = Qt[p * 68 + to * 4 + j];
            #pragma unroll
            for (int i = 0; i < 4; i++)
                #pragma unroll
                for (int j = 0; j < 4; j++)
                    acc[i][j] = fmaf(rk[i], rq[j], acc[i][j]);
        }
        const float nf = 0.08838834764831845f;
        #pragma unroll
        for (int i = 0; i < 4; i++) {
            int k = tk * 4 + i;
            #pragma unroll
            for (int j = 0; j < 4; j++) {
                int o = to * 4 + j;
                float v = (k >= o) ? acc[i][j] : -10000.0f;
                v += P[(size_t)(k * 128) * T_DIM + (size_t)(o * 128)];
                S[k * 65 + o] = v * nf;
            }
        }
    }
    __syncthreads();

    if (tid < 64) {
        int o = tid;
        float mx = -3.402823466e38f;
        for (int k = 0; k < 64; k++) mx = fmaxf(mx, S[k * 65 + o]);
        float sum = 0.f;
        for (int k = 0; k < 64; k++) {
            float e = __expf(S[k * 65 + o] - mx);
            S[k * 65 + o] = e;
            sum += e;
        }
        float inv = 1.0f / sum;
        for (int k = 0; k < 64; k++) S[k * 65 + o] *= inv;
    }
    __syncthreads();

    {
        const int td = tid >> 4;
        const int tmm = tid & 15;
        float acc[4][8];
        #pragma unroll
        for (int i = 0; i < 4; i++)
            #pragma unroll
            for (int j = 0; j < 8; j++) acc[i][j] = 0.f;
        for (int k = 0; k < 64; k++) {
            float rs[4];
            #pragma unroll
            for (int i = 0; i < 4; i++) rs[i] = S[k * 65 + td * 4 + i];
            float4 v0 = *reinterpret_cast<const float4*>(Vs + k * 128 + tmm * 8);
            float4 v1 = *reinterpret_cast<const float4*>(Vs + k * 128 + tmm * 8 + 4);
            float rv[8] = {v0.x, v0.y, v0.z, v0.w, v1.x, v1.y, v1.z, v1.w};
            #pragma unroll
            for (int i = 0; i < 4; i++)
                #pragma unroll
                for (int j = 0; j < 8; j++)
                    acc[i][j] = fmaf(rs[i], rv[j], acc[i][j]);
        }
        #pragma unroll
        for (int i = 0; i < 4; i++) {
            int d = td * 4 + i;
            size_t orow = (size_t)bb * T_DIM + 2 * ((size_t)jseg * 64 + d);
            float* op = out + orow * DV + tmm * 8;
            *reinterpret_cast<float4*>(op)     = make_float4(acc[i][0], acc[i][1], acc[i][2], acc[i][3]);
            *reinterpret_cast<float4*>(op + 4) = make_float4(acc[i][4], acc[i][5], acc[i][6], acc[i][7]);
        }
    }
}

extern "C" void kernel_launch(void* const* d_in, const int* in_sizes, int n_in,
                              void* d_out, int out_size) {
    const float* x  = (const float*)d_in[0];   // x_in  [4, 8192, 1024]
    const float* P  = (const float*)d_in[1];   // P     [8192, 8192]
    const float* Wk = (const float*)d_in[2];   // Wk    [128, 1024]
    const float* Wq = (const float*)d_in[3];   // Wq    [128, 1024]
    const float* Wv = (const float*)d_in[4];   // Wv    [128, 1024]
    float* out = (float*)d_out;                // [4, 8192, 128] fp32

    zero_out_kernel<<<1024, 256>>>((float4*)out, out_size / 4);
    prep_w_kernel<<<1536, 256>>>(Wq, Wk, Wv);

    int gsm = 2 * 40960;                       // 80 KB double buffer
    cudaFuncSetAttribute(qkv_gemm_mma, cudaFuncAttributeMaxDynamicSharedMemorySize, gsm);
    dim3 gg(128, 3);
    qkv_gemm_mma<<<gg, 256, gsm>>>(x);

    int smem = (64 * 128 * 2 + 128 * 68 + 64 * 65) * (int)sizeof(float);
    cudaFuncSetAttribute(attn_kernel, cudaFuncAttributeMaxDynamicSharedMemorySize, smem);
    attn_kernel<<<256, 256, smem>>>(P, out);
}

// round 4
// speedup vs baseline: 1.9407x; 1.0515x over previous
#include <cuda_runtime.h>
#include <cuda_bf16.h>
#include <cstdint>

#define E_DIM 1024
#define T_DIM 8192

// Scratch: QKV for the 16384 dilated tokens, layout [row][384] = Q|K|V.
__device__ float g_qkv[16384 * 384];
// Pre-split weights, rows 0-127=Wq, 128-255=Wk, 256-383=Wv
__device__ __nv_bfloat16 g_whi[384 * 1024];
__device__ __nv_bfloat16 g_wlo[384 * 1024];
// Gathered positional bias p_bias[k][o]
__device__ float g_pbias[64 * 64];

__device__ __forceinline__ uint32_t smem_u32(const void* p) {
    uint32_t a;
    asm("{ .reg .u64 t; cvta.to.shared.u64 t, %1; cvt.u32.u64 %0, t; }" : "=r"(a) : "l"(p));
    return a;
}

#define LDSM4(r, addr) \
    asm volatile("ldmatrix.sync.aligned.m8n8.x4.shared.b16 {%0,%1,%2,%3}, [%4];" \
        : "=r"((r)[0]), "=r"((r)[1]), "=r"((r)[2]), "=r"((r)[3]) : "r"(addr))

#define MMA16816(c, a, b0, b1) \
    asm volatile("mma.sync.aligned.m16n8k16.row.col.f32.bf16.bf16.f32 " \
        "{%0,%1,%2,%3}, {%4,%5,%6,%7}, {%8,%9}, {%0,%1,%2,%3};" \
        : "+f"((c)[0]), "+f"((c)[1]), "+f"((c)[2]), "+f"((c)[3]) \
        : "r"((a)[0]), "r"((a)[1]), "r"((a)[2]), "r"((a)[3]), "r"(b0), "r"(b1))

__device__ __forceinline__ void cp16(uint32_t dst, const void* src) {
    asm volatile("cp.async.cg.shared.global [%0], [%1], 16;" :: "r"(dst), "l"(src));
}
#define CP_COMMIT() asm volatile("cp.async.commit_group;" ::: "memory")

__device__ __forceinline__ void split2(float a, float b, uint32_t& hi, uint32_t& lo) {
    __nv_bfloat162 h = __floats2bfloat162_rn(a, b);
    __nv_bfloat162 l = __floats2bfloat162_rn(a - __bfloat162float(h.x),
                                             b - __bfloat162float(h.y));
    hi = *reinterpret_cast<uint32_t*>(&h);
    lo = *reinterpret_cast<uint32_t*>(&l);
}

// prep: split weights to bf16 hi/lo; gather p_bias.
__global__ __launch_bounds__(256) void prep_kernel(
    const float* __restrict__ Wq, const float* __restrict__ Wk,
    const float* __restrict__ Wv, const float* __restrict__ P)
{
    int i = blockIdx.x * blockDim.x + threadIdx.x;
    if (i < 4096) {
        g_pbias[i] = P[(size_t)(i >> 6) * 128 * T_DIM + (size_t)(i & 63) * 128];
    }
    if (i >= 384 * 1024) return;
    int r = i >> 10;
    const float* W = (r < 128) ? Wq : (r < 256) ? Wk : Wv;
    float v = W[(size_t)(r & 127) * 1024 + (i & 1023)];
    __nv_bfloat16 h = __float2bfloat16(v);
    g_whi[i] = h;
    g_wlo[i] = __float2bfloat16(v - __bfloat162float(h));
}

// ---- GEMM: C[16384,384] = Xdil * W^T, bf16 3-split HMMA, cp.async 4-stage ----
// Stage layout: A fp32 [128 rows x 144B] @0 (18432B);
//               Bhi [128 x 80B] @18432; Blo @28672. Stage = 38912B. 4 stages.
#define STG   38912
#define BH_OFF 18432

__global__ __launch_bounds__(256) void qkv_gemm_mma(const float* __restrict__ x)
{
    extern __shared__ char dsm[];
    const uint32_t smem_base = smem_u32(dsm);
    const int tid = threadIdx.x;
    const int warp = tid >> 5, lane = tid & 31;
    const int nbase = blockIdx.x * 128;      // slab (fast dim): 0=Q,128=K,256=V
    const int m0 = blockIdx.y * 128;

    // cp.async source pointers: A 4 rows/thread, B 2 rows/thread (hi+lo)
    const float* axp[4];
    const int arow_sub = tid >> 3;           // 0..31
    #pragma unroll
    for (int q = 0; q < 4; q++) {
        int r = m0 + arow_sub + q * 32;
        int b = r >> 12, j = (r >> 6) & 63, l = r & 63;
        axp[q] = x + ((size_t)b * T_DIM + (size_t)l * 128 + j) * E_DIM + (tid & 7) * 4;
    }
    const int brow_sub = tid >> 2;           // 0..63
    const __nv_bfloat16 *bhp[2], *blp[2];
    #pragma unroll
    for (int q = 0; q < 2; q++) {
        size_t off = (size_t)(nbase + brow_sub + q * 64) * 1024 + (tid & 3) * 8;
        bhp[q] = g_whi + off;
        blp[q] = g_wlo + off;
    }
    const uint32_t a_dst0 = arow_sub * 144 + (tid & 7) * 16;
    const uint32_t b_dst0 = brow_sub * 80 + (tid & 3) * 16;

    auto issue_stage = [&](int slot, int k0) {
        uint32_t sb = smem_base + slot * STG;
        #pragma unroll
        for (int q = 0; q < 4; q++)
            cp16(sb + a_dst0 + q * 4608, axp[q] + k0);
        #pragma unroll
        for (int q = 0; q < 2; q++) {
            cp16(sb + BH_OFF + b_dst0 + q * 5120, bhp[q] + k0);
            cp16(sb + BH_OFF + 10240 + b_dst0 + q * 5120, blp[q] + k0);
        }
    };

    // warp grid 4(M) x 2(N), warp tile 32x64
    const int m_w = (warp >> 1) * 32;
    const int n_w = (warp & 1) * 64;

    float acc[2][8][4];
    #pragma unroll
    for (int i = 0; i < 2; i++)
        #pragma unroll
        for (int j = 0; j < 8; j++)
            #pragma unroll
            for (int k = 0; k < 4; k++) acc[i][j][k] = 0.f;

    #pragma unroll
    for (int s = 0; s < 3; s++) { issue_stage(s, s * 32); CP_COMMIT(); }

    for (int c = 0; c < 32; c++) {
        asm volatile("cp.async.wait_group 2;" ::: "memory");
        __syncthreads();
        if (c < 29) issue_stage((c + 3) & 3, (c + 3) * 32);
        CP_COMMIT();

        const int slot = c & 3;
        const float* Asm = reinterpret_cast<const float*>(dsm + slot * STG);
        const uint32_t bb = smem_base + slot * STG + BH_OFF;

        #pragma unroll
        for (int kst = 0; kst < 2; kst++) {
            uint32_t ah[2][4], al[2][4];
            #pragma unroll
            for (int mt = 0; mt < 2; mt++) {
                const float* ap = Asm + (m_w + mt * 16 + (lane >> 2)) * 36
                                + kst * 16 + (lane & 3) * 2;
                float2 v00 = *reinterpret_cast<const float2*>(ap);
                float2 v10 = *reinterpret_cast<const float2*>(ap + 8 * 36);
                float2 v01 = *reinterpret_cast<const float2*>(ap + 8);
                float2 v11 = *reinterpret_cast<const float2*>(ap + 8 * 36 + 8);
                split2(v00.x, v00.y, ah[mt][0], al[mt][0]);
                split2(v10.x, v10.y, ah[mt][1], al[mt][1]);
                split2(v01.x, v01.y, ah[mt][2], al[mt][2]);
                split2(v11.x, v11.y, ah[mt][3], al[mt][3]);
            }
            #pragma unroll
            for (int nh = 0; nh < 2; nh++) {
                uint32_t bh[2][4], bl[2][4];
                #pragma unroll
                for (int q = 0; q < 2; q++) {
                    uint32_t rb = bb + (n_w + nh * 32 + q * 16 + (lane & 15)) * 80
                                + kst * 32 + (lane >> 4) * 16;
                    LDSM4(bh[q], rb);
                    LDSM4(bl[q], rb + 10240);
                }
                #pragma unroll
                for (int mt = 0; mt < 2; mt++)
                    #pragma unroll
                    for (int t = 0; t < 4; t++) {
                        const int q = t >> 1, s = t & 1;
                        const int nt = nh * 4 + q * 2 + s;
                        MMA16816(acc[mt][nt], ah[mt], bh[q][s], bh[q][s + 2]);
                        MMA16816(acc[mt][nt], ah[mt], bl[q][s], bl[q][s + 2]);
                        MMA16816(acc[mt][nt], al[mt], bh[q][s], bh[q][s + 2]);
                    }
            }
        }
    }

    // epilogue
    #pragma unroll
    for (int mt = 0; mt < 2; mt++) {
        #pragma unroll
        for (int nt = 0; nt < 8; nt++) {
            int row0 = m0 + m_w + mt * 16 + (lane >> 2);
            int col = nbase + n_w + nt * 8 + (lane & 3) * 2;
            float* p0 = &g_qkv[(size_t)row0 * 384 + col];
            float* p1 = &g_qkv[(size_t)(row0 + 8) * 384 + col];
            *reinterpret_cast<float2*>(p0) = make_float2(acc[mt][nt][0], acc[mt][nt][1]);
            *reinterpret_cast<float2*>(p1) = make_float2(acc[mt][nt][2], acc[mt][nt][3]);
        }
    }
}

// ---- attention: one block per (b,j) group; 2 CTAs/SM; fused odd-row zeroing ----
__global__ __launch_bounds__(256) void attn_kernel(float* __restrict__ out)
{
    extern __shared__ float sm[];
    float* Ks  = sm;                 // [64][128]
    float* Vs  = Ks + 64 * 128;      // [64][128]
    float* QtS = Vs + 64 * 128;      // [128][65] Qt, later overlaid by S[64][65]
    const int g = blockIdx.x;
    const int bbk = g >> 6, jseg = g & 63;
    const int tid = threadIdx.x;
    const float* base = g_qkv + (size_t)g * 64 * 384;

    for (int idx = tid; idx < 64 * 32; idx += 256) {
        int row = idx >> 5;
        int c4 = (idx & 31) * 4;
        const float* rp = base + (size_t)row * 384;
        float4 qv = *reinterpret_cast<const float4*>(rp + c4);
        float4 kv = *reinterpret_cast<const float4*>(rp + 128 + c4);
        float4 vv = *reinterpret_cast<const float4*>(rp + 256 + c4);
        *reinterpret_cast<float4*>(Ks + row * 128 + c4) = kv;
        *reinterpret_cast<float4*>(Vs + row * 128 + c4) = vv;
        QtS[(c4 + 0) * 65 + row] = qv.x;
        QtS[(c4 + 1) * 65 + row] = qv.y;
        QtS[(c4 + 2) * 65 + row] = qv.z;
        QtS[(c4 + 3) * 65 + row] = qv.w;
    }
    __syncthreads();

    // S[k][o] = dot(K[k], Q[o]) in regs; then mask + bias + scale
    const int tk = tid >> 4, to = tid & 15;
    float sval[4][4];
    {
        float sacc[4][4];
        #pragma unroll
        for (int i = 0; i < 4; i++)
            #pragma unroll
            for (int j = 0; j < 4; j++) sacc[i][j] = 0.f;
        for (int p = 0; p < 128; p++) {
            float rk[4], rq[4];
            #pragma unroll
            for (int i = 0; i < 4; i++) rk[i] = Ks[(tk * 4 + i) * 128 + p];
            #pragma unroll
            for (int j = 0; j < 4; j++) rq[j] = QtS[p * 65 + to * 4 + j];
            #pragma unroll
            for (int i = 0; i < 4; i++)
                #pragma unroll
                for (int j = 0; j < 4; j++)
                    sacc[i][j] = fmaf(rk[i], rq[j], sacc[i][j]);
        }
        const float nf = 0.08838834764831845f;  // 1/sqrt(128)
        #pragma unroll
        for (int i = 0; i < 4; i++) {
            int k = tk * 4 + i;
            #pragma unroll
            for (int j = 0; j < 4; j++) {
                int o = to * 4 + j;
                float v = (k >= o) ? sacc[i][j] : -10000.0f;
                v += g_pbias[k * 64 + o];
                sval[i][j] = v * nf;
            }
        }
    }
    __syncthreads();   // all threads done reading Qt
    #pragma unroll
    for (int i = 0; i < 4; i++)
        #pragma unroll
        for (int j = 0; j < 4; j++)
            QtS[(tk * 4 + i) * 65 + to * 4 + j] = sval[i][j];
    __syncthreads();

    // softmax over k: o = tid>>2, 4 lanes x 16 k each, shfl-bfly reduce
    {
        const int o = tid >> 2, seg = tid & 3;
        float e[16];
        float mx = -3.402823466e38f;
        #pragma unroll
        for (int i = 0; i < 16; i++) {
            e[i] = QtS[(seg * 16 + i) * 65 + o];
            mx = fmaxf(mx, e[i]);
        }
        mx = fmaxf(mx, __shfl_xor_sync(0xffffffffu, mx, 1));
        mx = fmaxf(mx, __shfl_xor_sync(0xffffffffu, mx, 2));
        float ssum = 0.f;
        #pragma unroll
        for (int i = 0; i < 16; i++) { e[i] = __expf(e[i] - mx); ssum += e[i]; }
        ssum += __shfl_xor_sync(0xffffffffu, ssum, 1);
        ssum += __shfl_xor_sync(0xffffffffu, ssum, 2);
        float inv = 1.0f / ssum;
        #pragma unroll
        for (int i = 0; i < 16; i++)
            QtS[(seg * 16 + i) * 65 + o] = e[i] * inv;
    }
    __syncthreads();

    // att[d][m] = sum_k S[k][d] * V[k][m]; write even row, zero odd row
    {
        const int td = tid >> 4, tmm = tid & 15;
        float acc[4][8];
        #pragma unroll
        for (int i = 0; i < 4; i++)
            #pragma unroll
            for (int j = 0; j < 8; j++) acc[i][j] = 0.f;
        for (int k = 0; k < 64; k++) {
            float rs[4];
            #pragma unroll
            for (int i = 0; i < 4; i++) rs[i] = QtS[k * 65 + td * 4 + i];
            float4 v0 = *reinterpret_cast<const float4*>(Vs + k * 128 + tmm * 8);
            float4 v1 = *reinterpret_cast<const float4*>(Vs + k * 128 + tmm * 8 + 4);
            float rv[8] = {v0.x, v0.y, v0.z, v0.w, v1.x, v1.y, v1.z, v1.w};
            #pragma unroll
            for (int i = 0; i < 4; i++)
                #pragma unroll
                for (int j = 0; j < 8; j++)
                    acc[i][j] = fmaf(rs[i], rv[j], acc[i][j]);
        }
        const float4 z = make_float4(0.f, 0.f, 0.f, 0.f);
        #pragma unroll
        for (int i = 0; i < 4; i++) {
            int d = td * 4 + i;
            size_t orow = (size_t)bbk * T_DIM + 2 * ((size_t)jseg * 64 + d);
            float* op = out + orow * 128 + tmm * 8;
            *reinterpret_cast<float4*>(op)     = make_float4(acc[i][0], acc[i][1], acc[i][2], acc[i][3]);
            *reinterpret_cast<float4*>(op + 4) = make_float4(acc[i][4], acc[i][5], acc[i][6], acc[i][7]);
            float* oz = op + 128;   // odd row (poisoned) -> zero
            *reinterpret_cast<float4*>(oz)     = z;
            *reinterpret_cast<float4*>(oz + 4) = z;
        }
    }
}

extern "C" void kernel_launch(void* const* d_in, const int* in_sizes, int n_in,
                              void* d_out, int out_size) {
    const float* x  = (const float*)d_in[0];   // x_in  [4, 8192, 1024]
    const float* P  = (const float*)d_in[1];   // P     [8192, 8192]
    const float* Wk = (const float*)d_in[2];   // Wk    [128, 1024]
    const float* Wq = (const float*)d_in[3];   // Wq    [128, 1024]
    const float* Wv = (const float*)d_in[4];   // Wv    [128, 1024]
    float* out = (float*)d_out;                // [4, 8192, 128] fp32

    prep_kernel<<<1536, 256>>>(Wq, Wk, Wv, P);

    int gsm = 4 * STG;                         // 155648 B
    cudaFuncSetAttribute(qkv_gemm_mma, cudaFuncAttributeMaxDynamicSharedMemorySize, gsm);
    qkv_gemm_mma<<<dim3(3, 128), 256, gsm>>>(x);

    int asm_sz = (64 * 128 * 2 + 128 * 65) * (int)sizeof(float);  // 98816
    cudaFuncSetAttribute(attn_kernel, cudaFuncAttributeMaxDynamicSharedMemorySize, asm_sz);
    attn_kernel<<<256, 256, asm_sz>>>(out);
}

// round 5
// speedup vs baseline: 2.0478x; 1.0552x over previous
#include <cuda_runtime.h>
#include <cuda_bf16.h>
#include <cstdint>

#define E_DIM 1024
#define T_DIM 8192

// Scratch: QKV for the 16384 dilated tokens, layout [row][384] = Q|K|V.
__device__ float g_qkv[16384 * 384];
// Pre-split weights, rows 0-127=Wq, 128-255=Wk, 256-383=Wv
__device__ __nv_bfloat16 g_whi[384 * 1024];
__device__ __nv_bfloat16 g_wlo[384 * 1024];
// Gathered positional bias p_bias[k][o]
__device__ float g_pbias[64 * 64];

__device__ __forceinline__ uint32_t smem_u32(const void* p) {
    uint32_t a;
    asm("{ .reg .u64 t; cvta.to.shared.u64 t, %1; cvt.u32.u64 %0, t; }" : "=r"(a) : "l"(p));
    return a;
}

#define LDSM4(r, addr) \
    asm volatile("ldmatrix.sync.aligned.m8n8.x4.shared.b16 {%0,%1,%2,%3}, [%4];" \
        : "=r"((r)[0]), "=r"((r)[1]), "=r"((r)[2]), "=r"((r)[3]) : "r"(addr))

#define MMA16816(c, a, b0, b1) \
    asm volatile("mma.sync.aligned.m16n8k16.row.col.f32.bf16.bf16.f32 " \
        "{%0,%1,%2,%3}, {%4,%5,%6,%7}, {%8,%9}, {%0,%1,%2,%3};" \
        : "+f"((c)[0]), "+f"((c)[1]), "+f"((c)[2]), "+f"((c)[3]) \
        : "r"((a)[0]), "r"((a)[1]), "r"((a)[2]), "r"((a)[3]), "r"(b0), "r"(b1))

__device__ __forceinline__ void cp16(uint32_t dst, const void* src) {
    asm volatile("cp.async.cg.shared.global [%0], [%1], 16;" :: "r"(dst), "l"(src));
}
#define CP_COMMIT() asm volatile("cp.async.commit_group;" ::: "memory")

__device__ __forceinline__ void split2(float a, float b, uint32_t& hi, uint32_t& lo) {
    __nv_bfloat162 h = __floats2bfloat162_rn(a, b);
    __nv_bfloat162 l = __floats2bfloat162_rn(a - __bfloat162float(h.x),
                                             b - __bfloat162float(h.y));
    hi = *reinterpret_cast<uint32_t*>(&h);
    lo = *reinterpret_cast<uint32_t*>(&l);
}

// prep: split weights to bf16 hi/lo; gather p_bias.
__global__ __launch_bounds__(256) void prep_kernel(
    const float* __restrict__ Wq, const float* __restrict__ Wk,
    const float* __restrict__ Wv, const float* __restrict__ P)
{
    int i = blockIdx.x * blockDim.x + threadIdx.x;
    if (i < 4096) {
        g_pbias[i] = P[(size_t)(i >> 6) * 128 * T_DIM + (size_t)(i & 63) * 128];
    }
    if (i >= 384 * 1024) return;
    int r = i >> 10;
    const float* W = (r < 128) ? Wq : (r < 256) ? Wk : Wv;
    float v = W[(size_t)(r & 127) * 1024 + (i & 1023)];
    __nv_bfloat16 h = __float2bfloat16(v);
    g_whi[i] = h;
    g_wlo[i] = __float2bfloat16(v - __bfloat162float(h));
}

// ---- GEMM: C[16384,384] = Xdil * W^T, bf16 3-split HMMA, cp.async 2-stage,
//      2 CTAs/SM. Stage: A fp32 [128x144B] @0; Bhi [128x80B] @18432; Blo @28672.
#define STG   38912
#define BH_OFF 18432

__global__ __launch_bounds__(256, 2) void qkv_gemm_mma(const float* __restrict__ x)
{
    extern __shared__ char dsm[];
    const uint32_t smem_base = smem_u32(dsm);
    const int tid = threadIdx.x;
    const int warp = tid >> 5, lane = tid & 31;
    const int nbase = blockIdx.x * 128;      // slab (fast dim): 0=Q,128=K,256=V
    const int m0 = blockIdx.y * 128;

    // cp.async source pointers: A 4 rows/thread, B 2 rows/thread (hi+lo)
    const float* axp[4];
    const int arow_sub = tid >> 3;           // 0..31
    #pragma unroll
    for (int q = 0; q < 4; q++) {
        int r = m0 + arow_sub + q * 32;
        int b = r >> 12, j = (r >> 6) & 63, l = r & 63;
        axp[q] = x + ((size_t)b * T_DIM + (size_t)l * 128 + j) * E_DIM + (tid & 7) * 4;
    }
    const int brow_sub = tid >> 2;           // 0..63
    const __nv_bfloat16 *bhp[2], *blp[2];
    #pragma unroll
    for (int q = 0; q < 2; q++) {
        size_t off = (size_t)(nbase + brow_sub + q * 64) * 1024 + (tid & 3) * 8;
        bhp[q] = g_whi + off;
        blp[q] = g_wlo + off;
    }
    const uint32_t a_dst0 = arow_sub * 144 + (tid & 7) * 16;
    const uint32_t b_dst0 = brow_sub * 80 + (tid & 3) * 16;

    auto issue_stage = [&](int slot, int k0) {
        uint32_t sb = smem_base + slot * STG;
        #pragma unroll
        for (int q = 0; q < 4; q++)
            cp16(sb + a_dst0 + q * 4608, axp[q] + k0);
        #pragma unroll
        for (int q = 0; q < 2; q++) {
            cp16(sb + BH_OFF + b_dst0 + q * 5120, bhp[q] + k0);
            cp16(sb + BH_OFF + 10240 + b_dst0 + q * 5120, blp[q] + k0);
        }
    };

    // warp grid 4(M) x 2(N), warp tile 32x64
    const int m_w = (warp >> 1) * 32;
    const int n_w = (warp & 1) * 64;

    float acc[2][8][4];
    #pragma unroll
    for (int i = 0; i < 2; i++)
        #pragma unroll
        for (int j = 0; j < 8; j++)
            #pragma unroll
            for (int k = 0; k < 4; k++) acc[i][j][k] = 0.f;

    issue_stage(0, 0);  CP_COMMIT();
    issue_stage(1, 32); CP_COMMIT();

    for (int c = 0; c < 32; c++) {
        asm volatile("cp.async.wait_group 1;" ::: "memory");
        __syncthreads();

        const int slot = c & 1;
        const float* Asm = reinterpret_cast<const float*>(dsm + slot * STG);
        const uint32_t bb = smem_base + slot * STG + BH_OFF;

        #pragma unroll
        for (int kst = 0; kst < 2; kst++) {
            uint32_t ah[2][4], al[2][4];
            #pragma unroll
            for (int mt = 0; mt < 2; mt++) {
                const float* ap = Asm + (m_w + mt * 16 + (lane >> 2)) * 36
                                + kst * 16 + (lane & 3) * 2;
                float2 v00 = *reinterpret_cast<const float2*>(ap);
                float2 v10 = *reinterpret_cast<const float2*>(ap + 8 * 36);
                float2 v01 = *reinterpret_cast<const float2*>(ap + 8);
                float2 v11 = *reinterpret_cast<const float2*>(ap + 8 * 36 + 8);
                split2(v00.x, v00.y, ah[mt][0], al[mt][0]);
                split2(v10.x, v10.y, ah[mt][1], al[mt][1]);
                split2(v01.x, v01.y, ah[mt][2], al[mt][2]);
                split2(v11.x, v11.y, ah[mt][3], al[mt][3]);
            }
            #pragma unroll
            for (int nh = 0; nh < 2; nh++) {
                uint32_t bh[2][4], bl[2][4];
                #pragma unroll
                for (int q = 0; q < 2; q++) {
                    uint32_t rb = bb + (n_w + nh * 32 + q * 16 + (lane & 15)) * 80
                                + kst * 32 + (lane >> 4) * 16;
                    LDSM4(bh[q], rb);
                    LDSM4(bl[q], rb + 10240);
                }
                // split-major ordering: 8 independent MMAs between acc reuse
                #pragma unroll
                for (int mt = 0; mt < 2; mt++)
                    #pragma unroll
                    for (int t = 0; t < 4; t++) {
                        const int q = t >> 1, s = t & 1;
                        MMA16816(acc[mt][nh * 4 + q * 2 + s], ah[mt], bh[q][s], bh[q][s + 2]);
                    }
                #pragma unroll
                for (int mt = 0; mt < 2; mt++)
                    #pragma unroll
                    for (int t = 0; t < 4; t++) {
                        const int q = t >> 1, s = t & 1;
                        MMA16816(acc[mt][nh * 4 + q * 2 + s], ah[mt], bl[q][s], bl[q][s + 2]);
                    }
                #pragma unroll
                for (int mt = 0; mt < 2; mt++)
                    #pragma unroll
                    for (int t = 0; t < 4; t++) {
                        const int q = t >> 1, s = t & 1;
                        MMA16816(acc[mt][nh * 4 + q * 2 + s], al[mt], bh[q][s], bh[q][s + 2]);
                    }
            }
        }

        __syncthreads();
        if (c < 30) issue_stage(slot, (c + 2) * 32);
        CP_COMMIT();
    }

    // epilogue
    #pragma unroll
    for (int mt = 0; mt < 2; mt++) {
        #pragma unroll
        for (int nt = 0; nt < 8; nt++) {
            int row0 = m0 + m_w + mt * 16 + (lane >> 2);
            int col = nbase + n_w + nt * 8 + (lane & 3) * 2;
            float* p0 = &g_qkv[(size_t)row0 * 384 + col];
            float* p1 = &g_qkv[(size_t)(row0 + 8) * 384 + col];
            *reinterpret_cast<float2*>(p0) = make_float2(acc[mt][nt][0], acc[mt][nt][1]);
            *reinterpret_cast<float2*>(p1) = make_float2(acc[mt][nt][2], acc[mt][nt][3]);
        }
    }
}

// ---- attention: one block per (b,j) group; fused odd-row zeroing ----
__global__ __launch_bounds__(256) void attn_kernel(float* __restrict__ out)
{
    extern __shared__ float sm[];
    float* Ks  = sm;                 // [64][128]
    float* Vs  = Ks + 64 * 128;      // [64][128]
    float* QtS = Vs + 64 * 128;      // [128][65] Qt, later overlaid by S[64][65]
    const int g = blockIdx.x;
    const int bbk = g >> 6, jseg = g & 63;
    const int tid = threadIdx.x;
    const float* base = g_qkv + (size_t)g * 64 * 384;

    for (int idx = tid; idx < 64 * 32; idx += 256) {
        int row = idx >> 5;
        int c4 = (idx & 31) * 4;
        const float* rp = base + (size_t)row * 384;
        float4 qv = *reinterpret_cast<const float4*>(rp + c4);
        float4 kv = *reinterpret_cast<const float4*>(rp + 128 + c4);
        float4 vv = *reinterpret_cast<const float4*>(rp + 256 + c4);
        *reinterpret_cast<float4*>(Ks + row * 128 + c4) = kv;
        *reinterpret_cast<float4*>(Vs + row * 128 + c4) = vv;
        QtS[(c4 + 0) * 65 + row] = qv.x;
        QtS[(c4 + 1) * 65 + row] = qv.y;
        QtS[(c4 + 2) * 65 + row] = qv.z;
        QtS[(c4 + 3) * 65 + row] = qv.w;
    }
    __syncthreads();

    // S[k][o] = dot(K[k], Q[o]) in regs; then mask + bias + scale
    const int tk = tid >> 4, to = tid & 15;
    float sval[4][4];
    {
        float sacc[4][4];
        #pragma unroll
        for (int i = 0; i < 4; i++)
            #pragma unroll
            for (int j = 0; j < 4; j++) sacc[i][j] = 0.f;
        for (int p = 0; p < 128; p++) {
            float rk[4], rq[4];
            #pragma unroll
            for (int i = 0; i < 4; i++) rk[i] = Ks[(tk * 4 + i) * 128 + p];
            #pragma unroll
            for (int j = 0; j < 4; j++) rq[j] = QtS[p * 65 + to * 4 + j];
            #pragma unroll
            for (int i = 0; i < 4; i++)
                #pragma unroll
                for (int j = 0; j < 4; j++)
                    sacc[i][j] = fmaf(rk[i], rq[j], sacc[i][j]);
        }
        const float nf = 0.08838834764831845f;  // 1/sqrt(128)
        #pragma unroll
        for (int i = 0; i < 4; i++) {
            int k = tk * 4 + i;
            #pragma unroll
            for (int j = 0; j < 4; j++) {
                int o = to * 4 + j;
                float v = (k >= o) ? sacc[i][j] : -10000.0f;
                v += g_pbias[k * 64 + o];
                sval[i][j] = v * nf;
            }
        }
    }
    __syncthreads();   // all threads done reading Qt
    #pragma unroll
    for (int i = 0; i < 4; i++)
        #pragma unroll
        for (int j = 0; j < 4; j++)
            QtS[(tk * 4 + i) * 65 + to * 4 + j] = sval[i][j];
    __syncthreads();

    // softmax over k: o = tid>>2, 4 lanes x 16 k each, shfl-bfly reduce
    {
        const int o = tid >> 2, seg = tid & 3;
        float e[16];
        float mx = -3.402823466e38f;
        #pragma unroll
        for (int i = 0; i < 16; i++) {
            e[i] = QtS[(seg * 16 + i) * 65 + o];
            mx = fmaxf(mx, e[i]);
        }
        mx = fmaxf(mx, __shfl_xor_sync(0xffffffffu, mx, 1));
        mx = fmaxf(mx, __shfl_xor_sync(0xffffffffu, mx, 2));
        float ssum = 0.f;
        #pragma unroll
        for (int i = 0; i < 16; i++) { e[i] = __expf(e[i] - mx); ssum += e[i]; }
        ssum += __shfl_xor_sync(0xffffffffu, ssum, 1);
        ssum += __shfl_xor_sync(0xffffffffu, ssum, 2);
        float inv = 1.0f / ssum;
        #pragma unroll
        for (int i = 0; i < 16; i++)
            QtS[(seg * 16 + i) * 65 + o] = e[i] * inv;
    }
    __syncthreads();

    // att[d][m] = sum_k S[k][d] * V[k][m]; write even row, zero odd row
    {
        const int td = tid >> 4, tmm = tid & 15;
        float acc[4][8];
        #pragma unroll
        for (int i = 0; i < 4; i++)
            #pragma unroll
            for (int j = 0; j < 8; j++) acc[i][j] = 0.f;
        for (int k = 0; k < 64; k++) {
            float rs[4];
            #pragma unroll
            for (int i = 0; i < 4; i++) rs[i] = QtS[k * 65 + td * 4 + i];
            float4 v0 = *reinterpret_cast<const float4*>(Vs + k * 128 + tmm * 8);
            float4 v1 = *reinterpret_cast<const float4*>(Vs + k * 128 + tmm * 8 + 4);
            float rv[8] = {v0.x, v0.y, v0.z, v0.w, v1.x, v1.y, v1.z, v1.w};
            #pragma unroll
            for (int i = 0; i < 4; i++)
                #pragma unroll
                for (int j = 0; j < 8; j++)
                    acc[i][j] = fmaf(rs[i], rv[j], acc[i][j]);
        }
        const float4 z = make_float4(0.f, 0.f, 0.f, 0.f);
        #pragma unroll
        for (int i = 0; i < 4; i++) {
            int d = td * 4 + i;
            size_t orow = (size_t)bbk * T_DIM + 2 * ((size_t)jseg * 64 + d);
            float* op = out + orow * 128 + tmm * 8;
            *reinterpret_cast<float4*>(op)     = make_float4(acc[i][0], acc[i][1], acc[i][2], acc[i][3]);
            *reinterpret_cast<float4*>(op + 4) = make_float4(acc[i][4], acc[i][5], acc[i][6], acc[i][7]);
            float* oz = op + 128;   // odd row (poisoned) -> zero
            *reinterpret_cast<float4*>(oz)     = z;
            *reinterpret_cast<float4*>(oz + 4) = z;
        }
    }
}

extern "C" void kernel_launch(void* const* d_in, const int* in_sizes, int n_in,
                              void* d_out, int out_size) {
    const float* x  = (const float*)d_in[0];   // x_in  [4, 8192, 1024]
    const float* P  = (const float*)d_in[1];   // P     [8192, 8192]
    const float* Wk = (const float*)d_in[2];   // Wk    [128, 1024]
    const float* Wq = (const float*)d_in[3];   // Wq    [128, 1024]
    const float* Wv = (const float*)d_in[4];   // Wv    [128, 1024]
    float* out = (float*)d_out;                // [4, 8192, 128] fp32

    prep_kernel<<<1536, 256>>>(Wq, Wk, Wv, P);

    int gsm = 2 * STG;                         // 77824 B -> 2 CTAs/SM
    cudaFuncSetAttribute(qkv_gemm_mma, cudaFuncAttributeMaxDynamicSharedMemorySize, gsm);
    qkv_gemm_mma<<<dim3(3, 128), 256, gsm>>>(x);

    int asm_sz = (64 * 128 * 2 + 128 * 65) * (int)sizeof(float);  // 98816
    cudaFuncSetAttribute(attn_kernel, cudaFuncAttributeMaxDynamicSharedMemorySize, asm_sz);
    attn_kernel<<<256, 256, asm_sz>>>(out);
}